// round 13
// baseline (speedup 1.0000x reference)
#include <cuda_runtime.h>

#define NN 1024
#define DD 256
#define DK 32       // d-chunk in shared
#define DHALF 128   // d-range per block (d-split by 2)

// scratch: normalized mu and sigma^2 = exp(log_sigma)
__device__ float g_mu[NN * DD];
__device__ float g_s[NN * DD];

typedef unsigned long long u64;

__device__ __forceinline__ float frcp(float x) {
    float r; asm("rcp.approx.ftz.f32 %0, %1;" : "=f"(r) : "f"(x)); return r;
}
__device__ __forceinline__ float flg2(float x) {
    float r; asm("lg2.approx.ftz.f32 %0, %1;" : "=f"(r) : "f"(x)); return r;
}
__device__ __forceinline__ void gred(float* p, float v) {
    asm volatile("red.global.add.f32 [%0], %1;" :: "l"(p), "f"(v) : "memory");
}
__device__ __forceinline__ u64 pk(float lo, float hi) {
    u64 r; asm("mov.b64 %0, {%1, %2};" : "=l"(r) : "f"(lo), "f"(hi)); return r;
}
__device__ __forceinline__ void upk(u64 v, float& lo, float& hi) {
    asm("mov.b64 {%0, %1}, %2;" : "=f"(lo), "=f"(hi) : "l"(v));
}
// packed math: fma.rn.f32x2 -> FFMA2
__device__ __forceinline__ u64 fma2(u64 a, u64 b, u64 c) {
    u64 r; asm("fma.rn.f32x2 %0, %1, %2, %3;" : "=l"(r) : "l"(a), "l"(b), "l"(c)); return r;
}

// warp-per-row prep: normalize mu_X row (eps=1e-12) and exp(log_sigma).
// 4 rows per 128-thread block -> 256 blocks.
__global__ void prep_kernel(const float* __restrict__ muX,
                            const float* __restrict__ logsig) {
    const int lane = threadIdx.x & 31;
    const int row = blockIdx.x * 4 + (threadIdx.x >> 5);
    const float4* mu4 = (const float4*)(muX    + row * DD);
    const float4* ls4 = (const float4*)(logsig + row * DD);
    float4 a = mu4[lane], b = mu4[lane + 32];
    float v = a.x*a.x + a.y*a.y + a.z*a.z + a.w*a.w
            + b.x*b.x + b.y*b.y + b.z*b.z + b.w*b.w;
    #pragma unroll
    for (int o = 16; o; o >>= 1) v += __shfl_xor_sync(0xffffffffu, v, o);
    float inv = rsqrtf(fmaxf(v, 1e-24f));   // == 1/max(||x||, 1e-12)
    float4* gm4 = (float4*)(g_mu + row * DD);
    float4* gs4 = (float4*)(g_s  + row * DD);
    gm4[lane]      = make_float4(a.x*inv, a.y*inv, a.z*inv, a.w*inv);
    gm4[lane + 32] = make_float4(b.x*inv, b.y*inv, b.z*inv, b.w*inv);
    float4 la = ls4[lane], lb = ls4[lane + 32];
    gs4[lane]      = make_float4(expf(la.x), expf(la.y), expf(la.z), expf(la.w));
    gs4[lane + 32] = make_float4(expf(lb.x), expf(lb.y), expf(lb.z), expf(lb.w));
}

__global__ void zero_kernel(float* __restrict__ out) {
    int i = blockIdx.x * 256 + threadIdx.x;
    ((float4*)out)[i] = make_float4(0.f, 0.f, 0.f, 0.f);
}

// 64x64 tile, 512 threads, 8 outputs/thread (2i x 4j). grid = 136 dense
// upper-triangular tiles x 2 d-halves (272 blocks, 2/SM). Partials RED-added
// into zeroed output. Packed fma.rn.f32x2 throughout; i-side operands stored
// PRE-DUPLICATED in smem (no pk movs); smem rows padded to 2 mod 32 words so
// all LDS.64 phases are bank-conflict-free. d-pair combine halves RCP; one
// lg2 per 16 d's via running product.
__global__ __launch_bounds__(512, 2) void pair_kernel(float* __restrict__ out) {
    // dense upper-triangular tile decode (16 tiles/side)
    const int b = blockIdx.x;
    int ti = (int)(16.5f - sqrtf(16.5f * 16.5f - 2.0f * (float)b + 0.25f));
    while (ti > 0 && b < (ti * (33 - ti)) / 2) ti--;
    while (b >= ((ti + 1) * (32 - ti)) / 2) ti++;
    const int tj = ti + (b - (ti * (33 - ti)) / 2);
    const int h = blockIdx.y;

    // i rows: 4 slots of 64 words (m0-dup, m1-dup, s0-dup, s1-dup; 2 words/d)
    // row = 256 + 2 pad = 258 words  (258 mod 32 == 2 -> conflict-free)
    // j rows: 2 slots of 64 words (mu-neg pair, s pair); 130 words (== 2 mod 32)
    __shared__ __align__(16) float s_i[32][258];
    __shared__ __align__(16) float s_j[32][130];

    const int t   = threadIdx.x;
    const int txj = t & 15;   // j pairs: txj, txj+16 -> j = 2txj,2txj+1,2txj+32,2txj+33
    const int ty  = t >> 4;   // i pair: i = 2ty, 2ty+1
    const int i0 = ti * 64, j0 = tj * 64;
    const int dbase = h * DHALF;

    const u64 ONE2  = pk(1.0f, 1.0f);
    const u64 ZERO2 = 0ull;
    const u64 LN2_2 = pk(0.6931471805599453f, 0.6931471805599453f);

    u64 acc2[2][2], prod2[2][2];
    #pragma unroll
    for (int k = 0; k < 2; k++)
        #pragma unroll
        for (int jp = 0; jp < 2; jp++) { acc2[k][jp] = ZERO2; prod2[k][jp] = ONE2; }

    for (int dc = 0; dc < DHALF; dc += DK) {
        __syncthreads();
        #pragma unroll
        for (int p = 0; p < 4; p++) {
            int idx = t + 512 * p;
            int d    = idx & 31;          // lane = d -> coalesced LDG, 2d-bank STS
            int pr   = (idx >> 5) & 31;
            int side = idx >> 10;
            int gd = dbase + dc + d;
            if (side == 0) {
                int r = (i0 + 2 * pr) * DD + gd;
                float m0 = g_mu[r], m1 = g_mu[r + DD];
                float s0 = g_s[r],  s1 = g_s[r + DD];
                *(float2*)&s_i[pr][      2 * d] = make_float2(m0, m0);
                *(float2*)&s_i[pr][ 64 + 2 * d] = make_float2(m1, m1);
                *(float2*)&s_i[pr][128 + 2 * d] = make_float2(s0, s0);
                *(float2*)&s_i[pr][192 + 2 * d] = make_float2(s1, s1);
            } else {
                int r = (j0 + 2 * pr) * DD + gd;
                *(float2*)&s_j[pr][     2 * d] = make_float2(-g_mu[r], -g_mu[r + DD]);
                *(float2*)&s_j[pr][64 + 2 * d] = make_float2( g_s[r],  g_s[r + DD]);
            }
        }
        __syncthreads();

        #pragma unroll 1
        for (int g = 0; g < 2; g++) {            // 16 d's per group; flush per group
            #pragma unroll
            for (int dp = 0; dp < 8; dp++) {     // d-pair (dA, dB)
                const int dA = g * 16 + 2 * dp;
                const int dB = dA + 1;
                // i side: pre-duplicated packed operands (broadcast LDS.64)
                u64 miA2[2], siA2[2], miB2[2], siB2[2];
                #pragma unroll
                for (int k = 0; k < 2; k++) {
                    miA2[k] = *(const u64*)&s_i[ty][ 64 * k +       2 * dA];
                    siA2[k] = *(const u64*)&s_i[ty][ 64 * k + 128 + 2 * dA];
                    miB2[k] = *(const u64*)&s_i[ty][ 64 * k +       2 * dB];
                    siB2[k] = *(const u64*)&s_i[ty][ 64 * k + 128 + 2 * dB];
                }
                // j side: packed pairs (conflict-free LDS.64)
                u64 mjA[2], sjA[2], mjB[2], sjB[2];
                #pragma unroll
                for (int jp = 0; jp < 2; jp++) {
                    const int r = txj + 16 * jp;
                    mjA[jp] = *(const u64*)&s_j[r][     2 * dA];
                    sjA[jp] = *(const u64*)&s_j[r][64 + 2 * dA];
                    mjB[jp] = *(const u64*)&s_j[r][     2 * dB];
                    sjB[jp] = *(const u64*)&s_j[r][64 + 2 * dB];
                }
                #pragma unroll
                for (int k = 0; k < 2; k++)
                    #pragma unroll
                    for (int jp = 0; jp < 2; jp++) {
                        u64 a  = fma2(siA2[k], ONE2, sjA[jp]);   // ssum @ dA
                        u64 bb = fma2(siB2[k], ONE2, sjB[jp]);   // ssum @ dB
                        u64 dA2 = fma2(miA2[k], ONE2, mjA[jp]);  // mu_i - mu_j
                        u64 dB2 = fma2(miB2[k], ONE2, mjB[jp]);
                        u64 sA = fma2(dA2, dA2, ZERO2);
                        u64 sB = fma2(dB2, dB2, ZERO2);
                        u64 den = fma2(a, bb, ZERO2);
                        u64 num = fma2(sA, bb, ZERO2);
                        num = fma2(sB, a, num);
                        float dl, dh; upk(den, dl, dh);
                        u64 rc = pk(frcp(dl), frcp(dh));
                        acc2[k][jp]  = fma2(num, rc, acc2[k][jp]);
                        prod2[k][jp] = fma2(prod2[k][jp], den, ZERO2);
                    }
            }
            // flush: acc += ln(prod of 16 ssums)
            #pragma unroll
            for (int k = 0; k < 2; k++)
                #pragma unroll
                for (int jp = 0; jp < 2; jp++) {
                    float pl, ph; upk(prod2[k][jp], pl, ph);
                    acc2[k][jp] = fma2(pk(flg2(pl), flg2(ph)), LN2_2, acc2[k][jp]);
                    prod2[k][jp] = ONE2;
                }
        }
    }

    // RED partial (-acc) into zero-initialized out; mirror unless diagonal tile.
    const bool diag = (ti == tj);
    #pragma unroll
    for (int k = 0; k < 2; k++) {
        int i = i0 + 2 * ty + k;
        #pragma unroll
        for (int jp = 0; jp < 2; jp++) {
            float v0, v1; upk(acc2[k][jp], v0, v1);
            int j = j0 + 2 * txj + 32 * jp;
            gred(&out[i * NN + j],     -v0);
            gred(&out[i * NN + j + 1], -v1);
            if (!diag) {
                gred(&out[j * NN + i],       -v0);
                gred(&out[(j + 1) * NN + i], -v1);
            }
        }
    }
}

extern "C" void kernel_launch(void* const* d_in, const int* in_sizes, int n_in,
                              void* d_out, int out_size) {
    const float* muX  = (const float*)d_in[0];
    const float* lsig = (const float*)d_in[1];
    float* out = (float*)d_out;

    prep_kernel<<<NN / 4, 128>>>(muX, lsig);
    zero_kernel<<<NN * NN / 4 / 256, 256>>>(out);

    dim3 grid(136, 2);   // dense triangular tiles x d-halves
    pair_kernel<<<grid, 512>>>(out);
}

// round 17
// speedup vs baseline: 1.0321x; 1.0321x over previous
#include <cuda_runtime.h>

#define NN 1024
#define DD 256
#define DK 32       // d-chunk in shared
#define DHALF 128   // d-range per block (d-split by 2)

// scratch: normalized mu and sigma^2 = exp(log_sigma)
__device__ float g_mu[NN * DD];
__device__ float g_s[NN * DD];

typedef unsigned long long u64;

__device__ __forceinline__ float frcp(float x) {
    float r; asm("rcp.approx.ftz.f32 %0, %1;" : "=f"(r) : "f"(x)); return r;
}
__device__ __forceinline__ float flg2(float x) {
    float r; asm("lg2.approx.ftz.f32 %0, %1;" : "=f"(r) : "f"(x)); return r;
}
__device__ __forceinline__ void gred(float* p, float v) {
    asm volatile("red.global.add.f32 [%0], %1;" :: "l"(p), "f"(v) : "memory");
}
__device__ __forceinline__ u64 pk(float lo, float hi) {
    u64 r; asm("mov.b64 %0, {%1, %2};" : "=l"(r) : "f"(lo), "f"(hi)); return r;
}
__device__ __forceinline__ void upk(u64 v, float& lo, float& hi) {
    asm("mov.b64 {%0, %1}, %2;" : "=f"(lo), "=f"(hi) : "l"(v));
}
// packed math: fma.rn.f32x2 -> FFMA2
__device__ __forceinline__ u64 fma2(u64 a, u64 b, u64 c) {
    u64 r; asm("fma.rn.f32x2 %0, %1, %2, %3;" : "=l"(r) : "l"(a), "l"(b), "l"(c)); return r;
}

// warp-per-row prep: normalize mu_X row (eps=1e-12) and exp(log_sigma).
__global__ void prep_kernel(const float* __restrict__ muX,
                            const float* __restrict__ logsig) {
    const int lane = threadIdx.x & 31;
    const int row = blockIdx.x * 4 + (threadIdx.x >> 5);
    const float4* mu4 = (const float4*)(muX    + row * DD);
    const float4* ls4 = (const float4*)(logsig + row * DD);
    float4 a = mu4[lane], b = mu4[lane + 32];
    float v = a.x*a.x + a.y*a.y + a.z*a.z + a.w*a.w
            + b.x*b.x + b.y*b.y + b.z*b.z + b.w*b.w;
    #pragma unroll
    for (int o = 16; o; o >>= 1) v += __shfl_xor_sync(0xffffffffu, v, o);
    float inv = rsqrtf(fmaxf(v, 1e-24f));   // == 1/max(||x||, 1e-12)
    float4* gm4 = (float4*)(g_mu + row * DD);
    float4* gs4 = (float4*)(g_s  + row * DD);
    gm4[lane]      = make_float4(a.x*inv, a.y*inv, a.z*inv, a.w*inv);
    gm4[lane + 32] = make_float4(b.x*inv, b.y*inv, b.z*inv, b.w*inv);
    float4 la = ls4[lane], lb = ls4[lane + 32];
    gs4[lane]      = make_float4(expf(la.x), expf(la.y), expf(la.z), expf(la.w));
    gs4[lane + 32] = make_float4(expf(lb.x), expf(lb.y), expf(lb.z), expf(lb.w));
}

__global__ void zero_kernel(float* __restrict__ out) {
    int i = blockIdx.x * 256 + threadIdx.x;
    ((float4*)out)[i] = make_float4(0.f, 0.f, 0.f, 0.f);
}

// 64x64 tile, 512 threads, 8 outputs/thread (2i x 4j). grid = 136 dense
// upper-triangular tiles x 2 d-halves (272 blocks, 2/SM). Partials RED-added
// into zeroed output. Packed fma.rn.f32x2 inner math; smem rows are 130 words
// (mu-pairs at [r][2d], s-pairs at [r][64+2d], 2-word pad): 130 == 2 mod 32,
// so j-side LDS.64 across 16 row-pairs covers all 32 banks exactly once.
// d-pair combine halves RCP; one lg2 per 16 d's via running product.
__global__ __launch_bounds__(512, 2) void pair_kernel(float* __restrict__ out) {
    // dense upper-triangular tile decode (16 tiles/side)
    const int b = blockIdx.x;
    int ti = (int)(16.5f - sqrtf(16.5f * 16.5f - 2.0f * (float)b + 0.25f));
    while (ti > 0 && b < (ti * (33 - ti)) / 2) ti--;
    while (b >= ((ti + 1) * (32 - ti)) / 2) ti++;
    const int tj = ti + (b - (ti * (33 - ti)) / 2);
    const int h = blockIdx.y;

    // per row-pair: words [0..63] = interleaved mu pair (2 words per d),
    //               words [64..127] = interleaved s pair, pad to 130.
    __shared__ __align__(8) float s_i[32][130];
    __shared__ __align__(8) float s_j[32][130];

    const int t   = threadIdx.x;
    const int txj = t & 15;   // j pairs: txj, txj+16 -> j = 2txj,2txj+1,2txj+32,2txj+33
    const int ty  = t >> 4;   // i pair: i = 2ty, 2ty+1
    const int i0 = ti * 64, j0 = tj * 64;
    const int dbase = h * DHALF;

    const u64 ONE2  = pk(1.0f, 1.0f);
    const u64 ZERO2 = 0ull;
    const u64 LN2_2 = pk(0.6931471805599453f, 0.6931471805599453f);

    u64 acc2[2][2], prod2[2][2];
    #pragma unroll
    for (int k = 0; k < 2; k++)
        #pragma unroll
        for (int jp = 0; jp < 2; jp++) { acc2[k][jp] = ZERO2; prod2[k][jp] = ONE2; }

    for (int dc = 0; dc < DHALF; dc += DK) {
        __syncthreads();
        #pragma unroll
        for (int p = 0; p < 4; p++) {
            int idx = t + 512 * p;
            int d    = idx & 31;          // lane = d -> coalesced LDG
            int pr   = (idx >> 5) & 31;
            int side = idx >> 10;
            int gd = dbase + dc + d;
            if (side == 0) {
                int r = (i0 + 2 * pr) * DD + gd;
                *(float2*)&s_i[pr][     2 * d] = make_float2(g_mu[r], g_mu[r + DD]);
                *(float2*)&s_i[pr][64 + 2 * d] = make_float2(g_s[r],  g_s[r + DD]);
            } else {
                int r = (j0 + 2 * pr) * DD + gd;
                *(float2*)&s_j[pr][     2 * d] = make_float2(-g_mu[r], -g_mu[r + DD]);
                *(float2*)&s_j[pr][64 + 2 * d] = make_float2( g_s[r],  g_s[r + DD]);
            }
        }
        __syncthreads();

        #pragma unroll 1
        for (int g = 0; g < 2; g++) {            // 16 d's per group; lg2 flush per group
            #pragma unroll 4
            for (int dp = 0; dp < 8; dp++) {     // d-pair (dA, dB)
                const int dA = g * 16 + 2 * dp;
                const int dB = dA + 1;
                // i side: pair loads (2-address broadcast), dup-pack per k
                float2 miA = *(const float2*)&s_i[ty][     2 * dA];
                float2 miB = *(const float2*)&s_i[ty][     2 * dB];
                float2 siA = *(const float2*)&s_i[ty][64 + 2 * dA];
                float2 siB = *(const float2*)&s_i[ty][64 + 2 * dB];
                u64 miA2[2] = { pk(miA.x, miA.x), pk(miA.y, miA.y) };
                u64 siA2[2] = { pk(siA.x, siA.x), pk(siA.y, siA.y) };
                u64 miB2[2] = { pk(miB.x, miB.x), pk(miB.y, miB.y) };
                u64 siB2[2] = { pk(siB.x, siB.x), pk(siB.y, siB.y) };
                // j side: packed pairs straight from shared (conflict-free LDS.64)
                u64 mjA[2], sjA[2], mjB[2], sjB[2];
                #pragma unroll
                for (int jp = 0; jp < 2; jp++) {
                    const int r = txj + 16 * jp;
                    mjA[jp] = *(const u64*)&s_j[r][     2 * dA];
                    sjA[jp] = *(const u64*)&s_j[r][64 + 2 * dA];
                    mjB[jp] = *(const u64*)&s_j[r][     2 * dB];
                    sjB[jp] = *(const u64*)&s_j[r][64 + 2 * dB];
                }
                #pragma unroll
                for (int k = 0; k < 2; k++)
                    #pragma unroll
                    for (int jp = 0; jp < 2; jp++) {
                        u64 a   = fma2(siA2[k], ONE2, sjA[jp]);  // ssum @ dA
                        u64 bb  = fma2(siB2[k], ONE2, sjB[jp]);  // ssum @ dB
                        u64 dA2 = fma2(miA2[k], ONE2, mjA[jp]);  // mu_i - mu_j
                        u64 dB2 = fma2(miB2[k], ONE2, mjB[jp]);
                        u64 sA = fma2(dA2, dA2, ZERO2);
                        u64 sB = fma2(dB2, dB2, ZERO2);
                        u64 den = fma2(a, bb, ZERO2);
                        u64 num = fma2(sA, bb, ZERO2);
                        num = fma2(sB, a, num);
                        float dl, dh; upk(den, dl, dh);
                        u64 rc = pk(frcp(dl), frcp(dh));
                        acc2[k][jp]  = fma2(num, rc, acc2[k][jp]);
                        prod2[k][jp] = fma2(prod2[k][jp], den, ZERO2);
                    }
            }
            // flush: acc += ln(prod of 16 ssums)
            #pragma unroll
            for (int k = 0; k < 2; k++)
                #pragma unroll
                for (int jp = 0; jp < 2; jp++) {
                    float pl, ph; upk(prod2[k][jp], pl, ph);
                    acc2[k][jp] = fma2(pk(flg2(pl), flg2(ph)), LN2_2, acc2[k][jp]);
                    prod2[k][jp] = ONE2;
                }
        }
    }

    // RED partial (-acc) into zero-initialized out; mirror unless diagonal tile.
    const bool diag = (ti == tj);
    #pragma unroll
    for (int k = 0; k < 2; k++) {
        int i = i0 + 2 * ty + k;
        #pragma unroll
        for (int jp = 0; jp < 2; jp++) {
            float v0, v1; upk(acc2[k][jp], v0, v1);
            int j = j0 + 2 * txj + 32 * jp;
            gred(&out[i * NN + j],     -v0);
            gred(&out[i * NN + j + 1], -v1);
            if (!diag) {
                gred(&out[j * NN + i],       -v0);
                gred(&out[(j + 1) * NN + i], -v1);
            }
        }
    }
}

extern "C" void kernel_launch(void* const* d_in, const int* in_sizes, int n_in,
                              void* d_out, int out_size) {
    const float* muX  = (const float*)d_in[0];
    const float* lsig = (const float*)d_in[1];
    float* out = (float*)d_out;

    prep_kernel<<<NN / 4, 128>>>(muX, lsig);
    zero_kernel<<<NN * NN / 4 / 256, 256>>>(out);

    dim3 grid(136, 2);   // dense triangular tiles x d-halves
    pair_kernel<<<grid, 512>>>(out);
}